// round 1
// baseline (speedup 1.0000x reference)
#include <cuda_runtime.h>
#include <cuda_bf16.h>
#include <cstdint>

// ---------------------------------------------------------------------------
// StackRNN fused kernel.
//
// Sizes (fixed): B=256, S=1024, HIDDEN=256, NUM_STATES=64, STACK_DEPTH=64,
// STACK_VOCAB=16, NUM_MEM_ACTIONS=18, VOCAB=128, FLAT=768.
//
// Output columns (N=210 total): n in [0,64)   -> next-state logits (w_st)
//                               n in [64,82)  -> mem-action logits (w_mem)
//                               n in [82,210) -> buffer logits     (w_buf)
//
// Precompute (prelude kernel):
//   E [128][210] : embed @ W[0:256, :]
//   CW[ 80][210] : rows 0..63 = w_state @ W[256:512,:], rows 64..79 = w_top @ W[512:768,:]
//   c [210]      : bias + b_state @ W[256:512,:] + b_top @ W[512:768,:]
// ---------------------------------------------------------------------------

#define NOUT 210
#define B_TOT 256
#define SEQ 1024

__device__ __align__(16) float g_E[128 * NOUT];
__device__ __align__(16) float g_CW[80 * NOUT];
__device__ __align__(16) float g_c[NOUT];

__global__ void precompute_kernel(
    const float* __restrict__ embed,
    const float* __restrict__ w_state, const float* __restrict__ b_state,
    const float* __restrict__ w_top,   const float* __restrict__ b_top,
    const float* __restrict__ w_mem,   const float* __restrict__ b_mem,
    const float* __restrict__ w_buf,   const float* __restrict__ b_buf,
    const float* __restrict__ w_st,    const float* __restrict__ b_st)
{
    __shared__ float wcol[768];
    int n = blockIdx.x;
    const float* W; const float* bias; int N, col;
    if (n < 64)       { W = w_st;  bias = b_st;  N = 64;  col = n; }
    else if (n < 82)  { W = w_mem; bias = b_mem; N = 18;  col = n - 64; }
    else              { W = w_buf; bias = b_buf; N = 128; col = n - 82; }

    int tid = threadIdx.x;
    for (int i = tid; i < 768; i += 256) wcol[i] = W[i * N + col];
    __syncthreads();

    if (tid < 128) {                      // E rows
        const float* er = embed + tid * 256;
        float s = 0.f;
        for (int h = 0; h < 256; h++) s += er[h] * wcol[h];
        g_E[tid * NOUT + n] = s;
    } else if (tid < 192) {               // state rows of CW
        int r = tid - 128;
        const float* wr = w_state + r * 256;
        float s = 0.f;
        for (int h = 0; h < 256; h++) s += wr[h] * wcol[256 + h];
        g_CW[r * NOUT + n] = s;
    } else if (tid < 208) {               // top rows of CW
        int r = tid - 192;
        const float* wr = w_top + r * 256;
        float s = 0.f;
        for (int h = 0; h < 256; h++) s += wr[h] * wcol[512 + h];
        g_CW[(64 + r) * NOUT + n] = s;
    } else if (tid == 208) {              // folded bias
        float s = bias[col];
        for (int h = 0; h < 256; h++) s += b_state[h] * wcol[256 + h];
        for (int h = 0; h < 256; h++) s += b_top[h]   * wcol[512 + h];
        g_c[n] = s;
    }
}

// Shared-memory layout (floats):
//   sE     @ 0       : 128*210 = 26880
//   sTok   @ 26880   : 2*1024 (ints)
//   sStack @ 28928   : [pp][g][d][v] 2*2*64*16 = 4096
//   sState @ 33024   : [g][64] = 128
//   sLog   @ 33152   : [g][96] = 192
//   sProb  @ 33344   : [g][32] = 64     ([0]=p_pop,[1]=p_noop,[2]=p_push,[4..19]=push probs)
//   total 33408 floats = 133632 bytes
#define SMEM_FLOATS 33408

__global__ __launch_bounds__(256, 1)
void stackrnn_kernel(const int* __restrict__ x, float* __restrict__ out)
{
    extern __shared__ float sm[];
    float* sE     = sm;
    int*   sTok   = (int*)(sm + 26880);
    float* sStack = sm + 28928;
    float* sState = sm + 33024;
    float* sLog   = sm + 33152;
    float* sProb  = sm + 33344;

    const int tid = threadIdx.x;
    const int b0 = blockIdx.x * 2;
    const int b1 = b0 + 1;

    // ---- one-time setup ----
    {
        const float4* src = (const float4*)g_E;
        float4* dst = (float4*)sE;
        for (int i = tid; i < (128 * NOUT) / 4; i += 256) dst[i] = src[i];
    }
    for (int i = tid; i < SEQ; i += 256) {
        sTok[i]       = x[(size_t)b0 * SEQ + i];
        sTok[SEQ + i] = x[(size_t)b1 * SEQ + i];
    }
    // stack ping buffer: every row = null one-hot (1 at v=0)
    for (int i = tid; i < 2048; i += 256) sStack[i] = ((i & 15) == 0) ? 1.f : 0.f;
    if (tid < 128) sState[tid] = 0.f;

    float w[80];
    float cn = 0.f;
    if (tid < NOUT) {
        cn = g_c[tid];
#pragma unroll
        for (int k = 0; k < 80; k++) w[k] = g_CW[k * NOUT + tid];
    }
    __syncthreads();

    int ping = 0;
    const int n = tid;
    const size_t outB0 = (size_t)b0 * (SEQ * 128);
    const size_t outB1 = (size_t)b1 * (SEQ * 128);

    for (int t = 0; t < SEQ; t++) {
        // ---------------- phase 1: 210 logits x 2 batches ----------------
        if (n < NOUT) {
            int tok0 = sTok[t], tok1 = sTok[SEQ + t];
            float a0  = cn + sE[tok0 * NOUT + n];
            float a1  = cn + sE[tok1 * NOUT + n];
            float a0b = 0.f, a0c = 0.f, a0d = 0.f;
            float a1b = 0.f, a1c = 0.f, a1d = 0.f;

            const float4* S0 = (const float4*)(sState);
            const float4* S1 = (const float4*)(sState + 64);
#pragma unroll
            for (int k4 = 0; k4 < 16; k4++) {
                float4 s0 = S0[k4];
                float4 s1 = S1[k4];
                a0  += w[4 * k4 + 0] * s0.x;  a0b += w[4 * k4 + 1] * s0.y;
                a0c += w[4 * k4 + 2] * s0.z;  a0d += w[4 * k4 + 3] * s0.w;
                a1  += w[4 * k4 + 0] * s1.x;  a1b += w[4 * k4 + 1] * s1.y;
                a1c += w[4 * k4 + 2] * s1.z;  a1d += w[4 * k4 + 3] * s1.w;
            }
            const float4* T0 = (const float4*)(sStack + ping * 2048);
            const float4* T1 = (const float4*)(sStack + ping * 2048 + 1024);
#pragma unroll
            for (int k4 = 0; k4 < 4; k4++) {
                float4 p0 = T0[k4];
                float4 p1 = T1[k4];
                a0  += w[64 + 4 * k4 + 0] * p0.x;  a0b += w[64 + 4 * k4 + 1] * p0.y;
                a0c += w[64 + 4 * k4 + 2] * p0.z;  a0d += w[64 + 4 * k4 + 3] * p0.w;
                a1  += w[64 + 4 * k4 + 0] * p1.x;  a1b += w[64 + 4 * k4 + 1] * p1.y;
                a1c += w[64 + 4 * k4 + 2] * p1.z;  a1d += w[64 + 4 * k4 + 3] * p1.w;
            }
            float r0 = (a0 + a0b) + (a0c + a0d);
            float r1 = (a1 + a1b) + (a1c + a1d);

            if (n < 82) {
                // logits are tiny (|.| < ~0.3): exp without max-subtraction is safe
                sLog[n]      = __expf(r0);
                sLog[96 + n] = __expf(r1);
            } else {
                int v = n - 82;
                out[outB0 + (size_t)t * 128 + v] = r0;
                out[outB1 + (size_t)t * 128 + v] = r1;
            }
        }
        __syncthreads();   // A : logits visible

        // ---------------- phase 2: softmaxes ----------------
        int wid = tid >> 5, lane = tid & 31;
        if (wid < 2) {
            // state softmax for batch g = wid (64 values)
            float* L = sLog + wid * 96;
            float e0 = L[lane], e1 = L[lane + 32];
            float s = e0 + e1;
#pragma unroll
            for (int o = 16; o; o >>= 1) s += __shfl_xor_sync(0xffffffffu, s, o);
            float inv = 1.0f / s;
            float* st = sState + wid * 64;
            st[lane]      = e0 * inv;
            st[lane + 32] = e1 * inv;
        } else if (wid < 4) {
            // mem-action softmax for batch g = wid-2 (18 values)
            int g = wid - 2;
            float* L = sLog + g * 96;
            float e = (lane < 18) ? L[64 + lane] : 0.f;
            float s = e;
#pragma unroll
            for (int o = 16; o; o >>= 1) s += __shfl_xor_sync(0xffffffffu, s, o);
            float e0 = __shfl_sync(0xffffffffu, e, 0);
            float e1 = __shfl_sync(0xffffffffu, e, 1);
            float inv = 1.0f / s;
            if (lane < 2)        sProb[g * 32 + lane]     = e * inv;   // pop, noop
            else if (lane < 18)  sProb[g * 32 + lane + 2] = e * inv;   // push probs at [4..19]
            if (lane == 0)       sProb[g * 32 + 2] = (s - e0 - e1) * inv; // p_push
        }
        __syncthreads();   // B : probs + new state ready

        // ---------------- phase 3: soft stack update ----------------
        if (tid < 64) {
            int g = tid >> 5;
            int r = tid & 31;
            int c = r & 3;          // float4 chunk of the 16-vocab row
            int d0 = (r >> 2) * 8;  // 8 depth rows per thread
            const float4* P = (const float4*)(sStack + ping * 2048 + g * 1024);
            float4*       Q = (float4*)(sStack + (ping ^ 1) * 2048 + g * 1024);
            float ppop  = sProb[g * 32 + 0];
            float pnoop = sProb[g * 32 + 1];
            float ppush = sProb[g * 32 + 2];
            float4 pv = ((const float4*)(sProb + g * 32 + 4))[c];

            float4 prev = (d0 == 0) ? make_float4(0.f, 0.f, 0.f, 0.f) : P[(d0 - 1) * 4 + c];
            float4 cur  = P[d0 * 4 + c];
#pragma unroll
            for (int i = 0; i < 8; i++) {
                int d = d0 + i;
                float4 nxt;
                if (d == 63) nxt = (c == 0) ? make_float4(1.f, 0.f, 0.f, 0.f)
                                            : make_float4(0.f, 0.f, 0.f, 0.f);
                else         nxt = P[(d + 1) * 4 + c];
                float4 o;
                o.x = ppush * prev.x + ppop * nxt.x + pnoop * cur.x;
                o.y = ppush * prev.y + ppop * nxt.y + pnoop * cur.y;
                o.z = ppush * prev.z + ppop * nxt.z + pnoop * cur.z;
                o.w = ppush * prev.w + ppop * nxt.w + pnoop * cur.w;
                if (d == 0) { o.x += pv.x; o.y += pv.y; o.z += pv.z; o.w += pv.w; }
                Q[d * 4 + c] = o;
                prev = cur; cur = nxt;
            }
        }
        __syncthreads();   // C : new stack ready
        ping ^= 1;
    }

    // ---------------- finals ----------------
    const size_t fsOff = (size_t)B_TOT * SEQ * 128;           // 33554432
    const size_t stOff = fsOff + (size_t)B_TOT * 64 * 16;     // 33816576
    for (int i = tid; i < 2048; i += 256) {
        int g = i >> 10, r = i & 1023;
        out[fsOff + (size_t)(b0 + g) * 1024 + r] = sStack[ping * 2048 + i];
    }
    if (tid < 128) {
        int g = tid >> 6, r = tid & 63;
        out[stOff + (size_t)(b0 + g) * 64 + r] = sState[tid];
    }
}

extern "C" void kernel_launch(void* const* d_in, const int* in_sizes, int n_in,
                              void* d_out, int out_size)
{
    const int*   x       = (const int*)  d_in[0];
    const float* embed   = (const float*)d_in[1];
    const float* w_state = (const float*)d_in[2];
    const float* b_state = (const float*)d_in[3];
    const float* w_top   = (const float*)d_in[4];
    const float* b_top   = (const float*)d_in[5];
    const float* w_mem   = (const float*)d_in[6];
    const float* b_mem   = (const float*)d_in[7];
    const float* w_buf   = (const float*)d_in[8];
    const float* b_buf   = (const float*)d_in[9];
    const float* w_st    = (const float*)d_in[10];
    const float* b_st    = (const float*)d_in[11];
    float* out = (float*)d_out;

    precompute_kernel<<<NOUT, 256>>>(embed, w_state, b_state, w_top, b_top,
                                     w_mem, b_mem, w_buf, b_buf, w_st, b_st);

    cudaFuncSetAttribute(stackrnn_kernel,
                         cudaFuncAttributeMaxDynamicSharedMemorySize,
                         SMEM_FLOATS * sizeof(float));
    stackrnn_kernel<<<B_TOT / 2, 256, SMEM_FLOATS * sizeof(float)>>>(x, out);
}

// round 2
// speedup vs baseline: 1.0187x; 1.0187x over previous
#include <cuda_runtime.h>
#include <cuda_bf16.h>
#include <cstdint>

// ---------------------------------------------------------------------------
// StackRNN fused kernel, v2: one barrier per step.
//
// Output columns (N=210): n in [0,64)   -> next-state logits (w_st)
//                         n in [64,82)  -> mem-action logits (w_mem)
//                         n in [82,210) -> buffer logits     (w_buf)
//
// Precompute: E[128][210] = embed @ W_top-part
//             CW[80][210] : rows 0..63 = w_state @ W_mid, 64..79 = w_top @ W_bot
//             c[210]      = bias + b_state@W_mid + b_top@W_bot
//
// Trick: softmaxes stored UNNORMALIZED (exps) + per-half partial sums Z.
// All consumers are linear in the softmax output, so invZ is folded into
// the consuming dot product / stack update. Every softmax is warp-local.
// ---------------------------------------------------------------------------

#define NOUT 210
#define B_TOT 256
#define SEQ 1024
#define NTHREADS 448

__device__ __align__(16) float g_E[128 * NOUT];
__device__ __align__(16) float g_CW[80 * NOUT];
__device__ __align__(16) float g_c[NOUT];

__global__ void precompute_kernel(
    const float* __restrict__ embed,
    const float* __restrict__ w_state, const float* __restrict__ b_state,
    const float* __restrict__ w_top,   const float* __restrict__ b_top,
    const float* __restrict__ w_mem,   const float* __restrict__ b_mem,
    const float* __restrict__ w_buf,   const float* __restrict__ b_buf,
    const float* __restrict__ w_st,    const float* __restrict__ b_st)
{
    __shared__ float wcol[768];
    int n = blockIdx.x;
    const float* W; const float* bias; int N, col;
    if (n < 64)       { W = w_st;  bias = b_st;  N = 64;  col = n; }
    else if (n < 82)  { W = w_mem; bias = b_mem; N = 18;  col = n - 64; }
    else              { W = w_buf; bias = b_buf; N = 128; col = n - 82; }

    int tid = threadIdx.x;
    for (int i = tid; i < 768; i += 256) wcol[i] = W[i * N + col];
    __syncthreads();

    if (tid < 128) {                      // E rows
        const float* er = embed + tid * 256;
        float s = 0.f;
        for (int h = 0; h < 256; h++) s += er[h] * wcol[h];
        g_E[tid * NOUT + n] = s;
    } else if (tid < 192) {               // state rows of CW
        int r = tid - 128;
        const float* wr = w_state + r * 256;
        float s = 0.f;
        for (int h = 0; h < 256; h++) s += wr[h] * wcol[256 + h];
        g_CW[r * NOUT + n] = s;
    } else if (tid < 208) {               // top rows of CW
        int r = tid - 192;
        const float* wr = w_top + r * 256;
        float s = 0.f;
        for (int h = 0; h < 256; h++) s += wr[h] * wcol[512 + h];
        g_CW[(64 + r) * NOUT + n] = s;
    } else if (tid == 208) {              // folded bias
        float s = bias[col];
        for (int h = 0; h < 256; h++) s += b_state[h] * wcol[256 + h];
        for (int h = 0; h < 256; h++) s += b_top[h]   * wcol[512 + h];
        g_c[n] = s;
    }
}

// Shared floats:
//   sE     @ 0     : 128*210 = 26880
//   sTok   @ 26880 : 2*1024 ints
//   sStack @ 28928 : [ping][g][64][16] = 4096   (NORMALIZED stack)
//   sState @ 33024 : [ping][g][64]     = 256    (UNNORMALIZED exps)
//   sZ     @ 33280 : [ping][g][2]      = 8      (partial sums of exps)
#define SMEM_FLOATS 33288

__global__ __launch_bounds__(NTHREADS, 1)
void stackrnn_kernel(const int* __restrict__ x, float* __restrict__ out)
{
    extern __shared__ float sm[];
    float* sE     = sm;
    int*   sTok   = (int*)(sm + 26880);
    float* sStack = sm + 28928;
    float* sState = sm + 33024;
    float* sZ     = sm + 33280;

    const int tid  = threadIdx.x;
    const int wid  = tid >> 5;
    const int lane = tid & 31;
    const int b0   = blockIdx.x * 2;

    // ---- one-time setup ----
    {
        const float4* src = (const float4*)g_E;
        float4* dst = (float4*)sE;
        for (int i = tid; i < (128 * NOUT) / 4; i += NTHREADS) dst[i] = src[i];
    }
    for (int i = tid; i < 2 * SEQ; i += NTHREADS) {
        int g = i >> 10, r = i & 1023;
        sTok[i] = x[(size_t)(b0 + g) * SEQ + r];
    }
    for (int i = tid; i < 2048; i += NTHREADS) sStack[i] = ((i & 15) == 0) ? 1.f : 0.f;
    if (tid < 128) sState[tid] = 0.f;          // exps=0, Z=1 -> state contribution 0
    if (tid < 4)   sZ[tid] = 0.5f;

    // ---- role assignment ----
    // wid 0..3 : state  (g = wid>>1, half h = wid&1, col = h*32+lane)
    // wid 4..5 : mem    (g = wid-4, col = 64+lane for lane<18) + stack update
    // wid 6..13: buf    (256 threads, g = (tid-192)>>7, col = 82 + v)
    const bool isState = (wid < 4);
    const bool isMem   = (wid == 4 || wid == 5);
    int g, mycol;
    if (isState)    { g = wid >> 1;  mycol = (wid & 1) * 32 + lane; }
    else if (isMem) { g = wid - 4;   mycol = 64 + (lane < 18 ? lane : 0); }
    else            { int idx = tid - 192; g = idx >> 7; mycol = 82 + (idx & 127); }

    float w[80];
    const float cn = g_c[mycol];
#pragma unroll
    for (int k = 0; k < 80; k++) w[k] = g_CW[k * NOUT + mycol];
    __syncthreads();

    int ping = 0;
    const size_t outB = (size_t)(b0 + g) * (SEQ * 128);

    for (int t = 0; t < SEQ; t++) {
        const int tok = sTok[g * SEQ + t];
        const float invZ = 1.0f / (sZ[ping * 4 + g * 2] + sZ[ping * 4 + g * 2 + 1]);
        const float base = cn + sE[tok * NOUT + mycol];

        const float4* S = (const float4*)(sState + ping * 128 + g * 64);
        const float4* T = (const float4*)(sStack + ping * 2048 + g * 1024);

        float a0 = 0.f, a1 = 0.f, a2 = 0.f, a3 = 0.f;
        float u0 = 0.f, u1 = 0.f, u2 = 0.f, u3 = 0.f;
#pragma unroll
        for (int k4 = 0; k4 < 16; k4++) {
            float4 s = S[k4];
            a0 += w[4 * k4 + 0] * s.x;  a1 += w[4 * k4 + 1] * s.y;
            a2 += w[4 * k4 + 2] * s.z;  a3 += w[4 * k4 + 3] * s.w;
        }
#pragma unroll
        for (int k4 = 0; k4 < 4; k4++) {
            float4 p = T[k4];
            u0 += w[64 + 4 * k4 + 0] * p.x;  u1 += w[64 + 4 * k4 + 1] * p.y;
            u2 += w[64 + 4 * k4 + 2] * p.z;  u3 += w[64 + 4 * k4 + 3] * p.w;
        }
        const float r = base + invZ * ((a0 + a1) + (a2 + a3)) + ((u0 + u1) + (u2 + u3));

        if (!isState && !isMem) {
            // -------- buffer logits: straight to gmem --------
            out[outB + (size_t)t * 128 + (mycol - 82)] = r;
        } else if (isState) {
            // -------- state: write exp + warp-partial Z --------
            float e = __expf(r);           // logits tiny; no max-subtract needed
            sState[(ping ^ 1) * 128 + g * 64 + mycol] = e;
            float ps = e;
#pragma unroll
            for (int o = 16; o; o >>= 1) ps += __shfl_xor_sync(0xffffffffu, ps, o);
            if (lane == 0) sZ[(ping ^ 1) * 4 + g * 2 + (wid & 1)] = ps;
        } else {
            // -------- mem action softmax (warp-local) + stack update --------
            float e = (lane < 18) ? __expf(r) : 0.f;
            float zs = e;
#pragma unroll
            for (int o = 16; o; o >>= 1) zs += __shfl_xor_sync(0xffffffffu, zs, o);
            const float iz = 1.0f / zs;
            const float e0 = __shfl_sync(0xffffffffu, e, 0);
            const float e1 = __shfl_sync(0xffffffffu, e, 1);
            const int c = lane & 3;
            float4 pv;
            pv.x = __shfl_sync(0xffffffffu, e, 2 + 4 * c + 0) * iz;
            pv.y = __shfl_sync(0xffffffffu, e, 2 + 4 * c + 1) * iz;
            pv.z = __shfl_sync(0xffffffffu, e, 2 + 4 * c + 2) * iz;
            pv.w = __shfl_sync(0xffffffffu, e, 2 + 4 * c + 3) * iz;
            const float ppop  = e0 * iz;
            const float pnoop = e1 * iz;
            const float ppush = (zs - e0 - e1) * iz;

            const int d0 = (lane >> 2) * 8;
            const float4* P = (const float4*)(sStack + ping * 2048 + g * 1024);
            float4*       Q = (float4*)(sStack + (ping ^ 1) * 2048 + g * 1024);

            float4 prev = (d0 == 0) ? make_float4(0.f, 0.f, 0.f, 0.f) : P[(d0 - 1) * 4 + c];
            float4 cur  = P[d0 * 4 + c];
#pragma unroll
            for (int i = 0; i < 8; i++) {
                int d = d0 + i;
                float4 nxt;
                if (d == 63) nxt = (c == 0) ? make_float4(1.f, 0.f, 0.f, 0.f)
                                            : make_float4(0.f, 0.f, 0.f, 0.f);
                else         nxt = P[(d + 1) * 4 + c];
                float4 o;
                o.x = ppush * prev.x + ppop * nxt.x + pnoop * cur.x;
                o.y = ppush * prev.y + ppop * nxt.y + pnoop * cur.y;
                o.z = ppush * prev.z + ppop * nxt.z + pnoop * cur.z;
                o.w = ppush * prev.w + ppop * nxt.w + pnoop * cur.w;
                if (d == 0) { o.x += pv.x; o.y += pv.y; o.z += pv.z; o.w += pv.w; }
                Q[d * 4 + c] = o;
                prev = cur; cur = nxt;
            }
        }
        __syncthreads();   // the ONLY barrier per step
        ping ^= 1;
    }

    // ---- finals ----
    const size_t fsOff = (size_t)B_TOT * SEQ * 128;
    const size_t stOff = fsOff + (size_t)B_TOT * 64 * 16;
    for (int i = tid; i < 2048; i += NTHREADS) {
        int gg = i >> 10, r = i & 1023;
        out[fsOff + (size_t)(b0 + gg) * 1024 + r] = sStack[ping * 2048 + i];
    }
    if (tid < 128) {
        int gg = tid >> 6;
        float invZ = 1.0f / (sZ[ping * 4 + gg * 2] + sZ[ping * 4 + gg * 2 + 1]);
        out[stOff + (size_t)(b0 + gg) * 64 + (tid & 63)] = sState[ping * 128 + tid] * invZ;
    }
}

extern "C" void kernel_launch(void* const* d_in, const int* in_sizes, int n_in,
                              void* d_out, int out_size)
{
    const int*   x       = (const int*)  d_in[0];
    const float* embed   = (const float*)d_in[1];
    const float* w_state = (const float*)d_in[2];
    const float* b_state = (const float*)d_in[3];
    const float* w_top   = (const float*)d_in[4];
    const float* b_top   = (const float*)d_in[5];
    const float* w_mem   = (const float*)d_in[6];
    const float* b_mem   = (const float*)d_in[7];
    const float* w_buf   = (const float*)d_in[8];
    const float* b_buf   = (const float*)d_in[9];
    const float* w_st    = (const float*)d_in[10];
    const float* b_st    = (const float*)d_in[11];
    float* out = (float*)d_out;

    precompute_kernel<<<NOUT, 256>>>(embed, w_state, b_state, w_top, b_top,
                                     w_mem, b_mem, w_buf, b_buf, w_st, b_st);

    cudaFuncSetAttribute(stackrnn_kernel,
                         cudaFuncAttributeMaxDynamicSharedMemorySize,
                         SMEM_FLOATS * sizeof(float));
    stackrnn_kernel<<<B_TOT / 2, NTHREADS, SMEM_FLOATS * sizeof(float)>>>(x, out);
}

// round 3
// speedup vs baseline: 1.3577x; 1.3328x over previous
#include <cuda_runtime.h>
#include <cuda_bf16.h>
#include <cstdint>

// ---------------------------------------------------------------------------
// StackRNN fused kernel, v3: one barrier/step, stack update OFF critical path.
//
// Columns (N=210): [0,64) state logits, [64,82) mem-action, [82,210) buffer.
// Precompute: E[128][210], CW[80][210] (64 state rows + 16 top rows), c[210].
//
// Per step t (single __syncthreads at end):
//  - logit warps: r = c + E[tok] + invZs*(exps_state . w) + invZm*(top~ . w)
//  - state warps (0-3): write raw exp(r) + 8 partial Z sums
//  - mem warps (4-5): warp-local softmax (raw e + Z), update register head
//    rows h0,h1, emit top~_{t+1} (unnormalized, scale Z) to smem
//  - buf warps (6-13): store logits to gmem
//  - update warps (14-15): apply probs_{t-1} (raw e + Z from smem) to the
//    full stack, one step behind; epilogue pass produces stack_S.
// ---------------------------------------------------------------------------

#define NOUT 210
#define B_TOT 256
#define SEQ 1024
#define NTHREADS 512

__device__ __align__(16) float g_E[128 * NOUT];
__device__ __align__(16) float g_CW[80 * NOUT];
__device__ __align__(16) float g_c[NOUT];

__global__ void precompute_kernel(
    const float* __restrict__ embed,
    const float* __restrict__ w_state, const float* __restrict__ b_state,
    const float* __restrict__ w_top,   const float* __restrict__ b_top,
    const float* __restrict__ w_mem,   const float* __restrict__ b_mem,
    const float* __restrict__ w_buf,   const float* __restrict__ b_buf,
    const float* __restrict__ w_st,    const float* __restrict__ b_st)
{
    __shared__ float wcol[768];
    int n = blockIdx.x;
    const float* W; const float* bias; int N, col;
    if (n < 64)       { W = w_st;  bias = b_st;  N = 64;  col = n; }
    else if (n < 82)  { W = w_mem; bias = b_mem; N = 18;  col = n - 64; }
    else              { W = w_buf; bias = b_buf; N = 128; col = n - 82; }

    int tid = threadIdx.x;
    for (int i = tid; i < 768; i += 256) wcol[i] = W[i * N + col];
    __syncthreads();

    if (tid < 128) {
        const float* er = embed + tid * 256;
        float s = 0.f;
        for (int h = 0; h < 256; h++) s += er[h] * wcol[h];
        g_E[tid * NOUT + n] = s;
    } else if (tid < 192) {
        int r = tid - 128;
        const float* wr = w_state + r * 256;
        float s = 0.f;
        for (int h = 0; h < 256; h++) s += wr[h] * wcol[256 + h];
        g_CW[r * NOUT + n] = s;
    } else if (tid < 208) {
        int r = tid - 192;
        const float* wr = w_top + r * 256;
        float s = 0.f;
        for (int h = 0; h < 256; h++) s += wr[h] * wcol[512 + h];
        g_CW[(64 + r) * NOUT + n] = s;
    } else if (tid == 208) {
        float s = bias[col];
        for (int h = 0; h < 256; h++) s += b_state[h] * wcol[256 + h];
        for (int h = 0; h < 256; h++) s += b_top[h]   * wcol[512 + h];
        g_c[n] = s;
    }
}

// Shared floats:
//   sE     @ 0     : 26880
//   sTok   @ 26880 : 2048 ints
//   sStack @ 28928 : [ping][g][64][16] = 4096
//   sSt    @ 33024 : [ping][g][64] = 256    raw state exps
//   sZs    @ 33280 : [ping][g][8]  = 32     partial state Z sums
//   sTop   @ 33312 : [ping][g][16] = 64     raw top~ (scale Zm)
//   sZm    @ 33376 : [ping][g]     = 4 (+4 pad)
//   sPr    @ 33384 : [ping][g][20] = 80     raw probs: [0]=e_pop,[1]=e_noop,
//                                           [2]=Z, [4..19]=e_push
#define SMEM_FLOATS 33464

__global__ __launch_bounds__(NTHREADS, 1)
void stackrnn_kernel(const int* __restrict__ x, float* __restrict__ out)
{
    extern __shared__ float sm[];
    float* sE     = sm;
    int*   sTok   = (int*)(sm + 26880);
    float* sStack = sm + 28928;
    float* sSt    = sm + 33024;
    float* sZs    = sm + 33280;
    float* sTop   = sm + 33312;
    float* sZm    = sm + 33376;
    float* sPr    = sm + 33384;

    const int tid  = threadIdx.x;
    const int wid  = tid >> 5;
    const int lane = tid & 31;
    const int b0   = blockIdx.x * 2;

    // ---- one-time setup ----
    {
        const float4* src = (const float4*)g_E;
        float4* dst = (float4*)sE;
        for (int i = tid; i < (128 * NOUT) / 4; i += NTHREADS) dst[i] = src[i];
    }
    for (int i = tid; i < 2 * SEQ; i += NTHREADS) {
        int g = i >> 10, r = i & 1023;
        sTok[i] = x[(size_t)(b0 + g) * SEQ + r];
    }
    for (int i = tid; i < 2048; i += NTHREADS) sStack[i] = ((i & 15) == 0) ? 1.f : 0.f;
    if (tid < 128) sSt[tid] = 0.f;                 // raw exps 0 -> contribution 0
    if (tid < 16)  sZs[tid] = 0.125f;              // Zs sums to 1
    if (tid < 64)  sTop[(tid >> 4) * 16 + (tid & 15)] = 0.f;
    if (tid < 4)   { int p = tid >> 1, g = tid & 1; sTop[p * 32 + g * 16] = 1.f; }
    if (tid < 2)   sZm[tid] = 1.f;
    if (tid < 80)  sPr[(tid / 20) * 20 + (tid % 20)] = 0.f;   // ping 0 init below
    __syncthreads();
    if (tid < 2) { sPr[tid * 20 + 1] = 1.f; sPr[tid * 20 + 2] = 1.f; }  // noop, Z=1

    // ---- roles ----
    const bool isState  = (wid < 4);
    const bool isMem    = (wid == 4 || wid == 5);
    const bool isUpdate = (wid >= 14);
    int g, mycol;
    if (isState)       { g = wid >> 1;  mycol = (wid & 1) * 32 + lane; }
    else if (isMem)    { g = wid - 4;   mycol = 64 + (lane < 18 ? lane : 0); }
    else if (isUpdate) { g = wid - 14;  mycol = 0; }
    else               { int idx = tid - 192; g = idx >> 7; mycol = 82 + (idx & 127); }

    float w[80];
    float cn = 0.f;
    if (!isUpdate) {
        cn = g_c[mycol];
#pragma unroll
        for (int k = 0; k < 80; k++) w[k] = g_CW[k * NOUT + mycol];
    }
    __syncthreads();

    // mem-warp carried head state (lanes 0-15 hold component v=lane)
    float h0r = (lane == 0) ? 1.f : 0.f;   // raw, scale Zp
    float h1r = (lane == 0) ? 1.f : 0.f;
    float e0p = 0.f, e1p = 1.f, Zp = 1.f;  // probs_{-1} = noop

    int ping = 0;
    const size_t outB = (size_t)(b0 + g) * (SEQ * 128);

    for (int t = 0; t < SEQ; t++) {
        if (isUpdate) {
            // ------- full stack update, one step behind (probs_{t-1}) -------
            const float* pr = sPr + ping * 40 + g * 20;
            float pe0 = pr[0], pe1 = pr[1], Zr = pr[2];
            float iz = __fdividef(1.f, Zr);
            float ppop  = pe0 * iz;
            float pnoop = pe1 * iz;
            float ppush = (Zr - pe0 - pe1) * iz;
            const int c = lane & 3;
            const int d0 = (lane >> 2) * 8;
            float4 pv = ((const float4*)(pr + 4))[c];
            pv.x *= iz; pv.y *= iz; pv.z *= iz; pv.w *= iz;

            const float4* P = (const float4*)(sStack + ping * 2048 + g * 1024);
            float4*       Q = (float4*)(sStack + (ping ^ 1) * 2048 + g * 1024);
            float4 prev = (d0 == 0) ? make_float4(0.f, 0.f, 0.f, 0.f) : P[(d0 - 1) * 4 + c];
            float4 cur  = P[d0 * 4 + c];
#pragma unroll
            for (int i = 0; i < 8; i++) {
                int d = d0 + i;
                float4 nxt;
                if (d == 63) nxt = (c == 0) ? make_float4(1.f, 0.f, 0.f, 0.f)
                                            : make_float4(0.f, 0.f, 0.f, 0.f);
                else         nxt = P[(d + 1) * 4 + c];
                float4 o;
                o.x = ppush * prev.x + ppop * nxt.x + pnoop * cur.x;
                o.y = ppush * prev.y + ppop * nxt.y + pnoop * cur.y;
                o.z = ppush * prev.z + ppop * nxt.z + pnoop * cur.z;
                o.w = ppush * prev.w + ppop * nxt.w + pnoop * cur.w;
                if (d == 0) { o.x += pv.x; o.y += pv.y; o.z += pv.z; o.w += pv.w; }
                Q[d * 4 + c] = o;
                prev = cur; cur = nxt;
            }
        } else {
            // ------- mem-warp pre-dot: normalize head, reconstruct row 2 -------
            float h0 = 0.f, h1 = 0.f, h2 = 0.f;
            if (isMem) {
                float izp = __fdividef(1.f, Zp);
                h0 = h0r * izp;  h1 = h1r * izp;
                float s1 = 0.f, s2 = 0.f, s3 = 0.f;
                if (lane < 16) {
                    const float* SB = sStack + ping * 2048 + g * 1024;
                    s1 = SB[16 + lane]; s2 = SB[32 + lane]; s3 = SB[48 + lane];
                }
                float ppm = (Zp - e0p - e1p) * izp;
                h2 = ppm * s1 + (e0p * izp) * s3 + (e1p * izp) * s2;
            }

            // ------- shared dot -------
            const int tok = sTok[g * SEQ + t];
            float zsum;
            {
                const float4* Z8 = (const float4*)(sZs + ping * 16 + g * 8);
                float4 za = Z8[0], zb = Z8[1];
                zsum = ((za.x + za.y) + (za.z + za.w)) + ((zb.x + zb.y) + (zb.z + zb.w));
            }
            const float invZs = __fdividef(1.f, zsum);
            const float invZm = __fdividef(1.f, sZm[ping * 2 + g]);
            const float base = cn + sE[tok * NOUT + mycol];

            const float4* S = (const float4*)(sSt + ping * 128 + g * 64);
            const float4* T = (const float4*)(sTop + ping * 32 + g * 16);
            float a0 = 0.f, a1 = 0.f, a2 = 0.f, a3 = 0.f;
            float a4 = 0.f, a5 = 0.f, a6 = 0.f, a7 = 0.f;
#pragma unroll
            for (int k8 = 0; k8 < 8; k8++) {
                float4 sA = S[2 * k8], sB = S[2 * k8 + 1];
                a0 += w[8 * k8 + 0] * sA.x;  a1 += w[8 * k8 + 1] * sA.y;
                a2 += w[8 * k8 + 2] * sA.z;  a3 += w[8 * k8 + 3] * sA.w;
                a4 += w[8 * k8 + 4] * sB.x;  a5 += w[8 * k8 + 5] * sB.y;
                a6 += w[8 * k8 + 6] * sB.z;  a7 += w[8 * k8 + 7] * sB.w;
            }
            float u0 = 0.f, u1 = 0.f, u2 = 0.f, u3 = 0.f;
#pragma unroll
            for (int k4 = 0; k4 < 4; k4++) {
                float4 p = T[k4];
                u0 += w[64 + 4 * k4 + 0] * p.x;  u1 += w[64 + 4 * k4 + 1] * p.y;
                u2 += w[64 + 4 * k4 + 2] * p.z;  u3 += w[64 + 4 * k4 + 3] * p.w;
            }
            float dS = ((a0 + a1) + (a2 + a3)) + ((a4 + a5) + (a6 + a7));
            float dT = (u0 + u1) + (u2 + u3);
            const float r = base + invZs * dS + invZm * dT;

            if (isState) {
                float e = __expf(r);
                sSt[(ping ^ 1) * 128 + g * 64 + mycol] = e;
                float ps = e;
                ps += __shfl_xor_sync(0xffffffffu, ps, 1);
                ps += __shfl_xor_sync(0xffffffffu, ps, 2);
                ps += __shfl_xor_sync(0xffffffffu, ps, 4);
                if ((lane & 7) == 0)
                    sZs[(ping ^ 1) * 16 + g * 8 + (wid & 1) * 4 + (lane >> 3)] = ps;
            } else if (isMem) {
                float e = (lane < 18) ? __expf(r) : 0.f;
                // broadcasts (independent of reduce chain)
                float e0 = __shfl_sync(0xffffffffu, e, 0);
                float e1 = __shfl_sync(0xffffffffu, e, 1);
                float ep = __shfl_sync(0xffffffffu, e, (2 + lane) & 31);
                float Zt = e;
                Zt += __shfl_xor_sync(0xffffffffu, Zt, 16);
                Zt += __shfl_xor_sync(0xffffffffu, Zt, 8);
                Zt += __shfl_xor_sync(0xffffffffu, Zt, 4);
                Zt += __shfl_xor_sync(0xffffffffu, Zt, 2);
                Zt += __shfl_xor_sync(0xffffffffu, Zt, 1);

                float topn = e1 * h0 + e0 * h1 + ep;                 // scale Zt
                float h1n  = (Zt - e0 - e1) * h0 + e0 * h2 + e1 * h1;

                if (lane < 16) sTop[(ping ^ 1) * 32 + g * 16 + lane] = topn;
                int pidx = (lane < 2) ? lane : lane + 2;
                if (lane < 18) sPr[(ping ^ 1) * 40 + g * 20 + pidx] = e;
                if (lane == 0) {
                    sPr[(ping ^ 1) * 40 + g * 20 + 2] = Zt;
                    sZm[(ping ^ 1) * 2 + g] = Zt;
                }
                h0r = topn; h1r = h1n; e0p = e0; e1p = e1; Zp = Zt;
            } else {
                out[outB + (size_t)t * 128 + (mycol - 82)] = r;
            }
        }
        __syncthreads();
        ping ^= 1;
    }

    // ---- epilogue: apply probs_{S-1} to stack_{S-1} -> stack_S ----
    if (isUpdate) {
        const float* pr = sPr + ping * 40 + g * 20;
        float pe0 = pr[0], pe1 = pr[1], Zr = pr[2];
        float iz = __fdividef(1.f, Zr);
        float ppop  = pe0 * iz;
        float pnoop = pe1 * iz;
        float ppush = (Zr - pe0 - pe1) * iz;
        const int c = lane & 3;
        const int d0 = (lane >> 2) * 8;
        float4 pv = ((const float4*)(pr + 4))[c];
        pv.x *= iz; pv.y *= iz; pv.z *= iz; pv.w *= iz;

        const float4* P = (const float4*)(sStack + ping * 2048 + g * 1024);
        float4*       Q = (float4*)(sStack + (ping ^ 1) * 2048 + g * 1024);
        float4 prev = (d0 == 0) ? make_float4(0.f, 0.f, 0.f, 0.f) : P[(d0 - 1) * 4 + c];
        float4 cur  = P[d0 * 4 + c];
#pragma unroll
        for (int i = 0; i < 8; i++) {
            int d = d0 + i;
            float4 nxt;
            if (d == 63) nxt = (c == 0) ? make_float4(1.f, 0.f, 0.f, 0.f)
                                        : make_float4(0.f, 0.f, 0.f, 0.f);
            else         nxt = P[(d + 1) * 4 + c];
            float4 o;
            o.x = ppush * prev.x + ppop * nxt.x + pnoop * cur.x;
            o.y = ppush * prev.y + ppop * nxt.y + pnoop * cur.y;
            o.z = ppush * prev.z + ppop * nxt.z + pnoop * cur.z;
            o.w = ppush * prev.w + ppop * nxt.w + pnoop * cur.w;
            if (d == 0) { o.x += pv.x; o.y += pv.y; o.z += pv.z; o.w += pv.w; }
            Q[d * 4 + c] = o;
            prev = cur; cur = nxt;
        }
    }
    __syncthreads();

    // ---- finals ----
    const size_t fsOff = (size_t)B_TOT * SEQ * 128;
    const size_t stOff = fsOff + (size_t)B_TOT * 64 * 16;
    for (int i = tid; i < 2048; i += NTHREADS) {
        int gg = i >> 10, r = i & 1023;
        out[fsOff + (size_t)(b0 + gg) * 1024 + r] = sStack[(ping ^ 1) * 2048 + i];
    }
    if (tid < 128) {
        int gg = tid >> 6;
        float zsum = 0.f;
        for (int k = 0; k < 8; k++) zsum += sZs[ping * 16 + gg * 8 + k];
        out[stOff + (size_t)(b0 + gg) * 64 + (tid & 63)] =
            sSt[ping * 128 + tid] * __fdividef(1.f, zsum);
    }
}

extern "C" void kernel_launch(void* const* d_in, const int* in_sizes, int n_in,
                              void* d_out, int out_size)
{
    const int*   x       = (const int*)  d_in[0];
    const float* embed   = (const float*)d_in[1];
    const float* w_state = (const float*)d_in[2];
    const float* b_state = (const float*)d_in[3];
    const float* w_top   = (const float*)d_in[4];
    const float* b_top   = (const float*)d_in[5];
    const float* w_mem   = (const float*)d_in[6];
    const float* b_mem   = (const float*)d_in[7];
    const float* w_buf   = (const float*)d_in[8];
    const float* b_buf   = (const float*)d_in[9];
    const float* w_st    = (const float*)d_in[10];
    const float* b_st    = (const float*)d_in[11];
    float* out = (float*)d_out;

    precompute_kernel<<<NOUT, 256>>>(embed, w_state, b_state, w_top, b_top,
                                     w_mem, b_mem, w_buf, b_buf, w_st, b_st);

    cudaFuncSetAttribute(stackrnn_kernel,
                         cudaFuncAttributeMaxDynamicSharedMemorySize,
                         SMEM_FLOATS * sizeof(float));
    stackrnn_kernel<<<B_TOT / 2, NTHREADS, SMEM_FLOATS * sizeof(float)>>>(x, out);
}